// round 1
// baseline (speedup 1.0000x reference)
#include <cuda_runtime.h>
#include <math.h>

// Problem constants (match reference)
#define OUT_H 7
#define OUT_W 7
#define GG 2              // SAMPLE_NUM
#define NBINS (OUT_H*OUT_W)          // 49
#define NSAMP (NBINS*GG*GG)          // 196
#define C_ 256
#define H_ 200
#define W_ 200
#define HW (H_*W_)
#define SPATIAL_SCALE 0.25f

// Block = one roi. 256 threads.
// Phase 1: threads 0..195 build per-sample bilinear metadata into shared (SoA).
// Phase 2: 49 iterations; element e = j*256+tid -> c = e/49, bin = e%49.
//          bin is lane-fastest => coalesced writes, spatially-local gathers.
__global__ __launch_bounds__(256, 8)
void roi_align_rotated_kernel(const float* __restrict__ feat,
                              const float* __restrict__ rois,
                              float* __restrict__ out)
{
    __shared__ int   s_off[NSAMP];   // base corner offset yl*W + xl
    __shared__ int   s_pk [NSAMP];   // dx | (dy*W << 4)
    __shared__ float s_lx [NSAMP];
    __shared__ float s_ly [NSAMP];
    __shared__ float s_sc [NSAMP];   // valid ? 0.25 : 0  (folds the g*g mean)
    __shared__ int   s_bofs;         // batch base offset (elements)

    const int r = blockIdx.x;
    const int t = threadIdx.x;

    if (t < NSAMP) {
        const float* rr = rois + r * 6;
        float cx = rr[1] * SPATIAL_SCALE - 0.5f;
        float cy = rr[2] * SPATIAL_SCALE - 0.5f;
        float rw = rr[3] * SPATIAL_SCALE;
        float rh = rr[4] * SPATIAL_SCALE;
        float th = rr[5];
        float sn, cs;
        sincosf(th, &sn, &cs);

        if (t == 0) {
            s_bofs = (int)rr[0] * (C_ * HW);
        }

        int bin = t >> 2;            // 0..48
        int sub = t & 3;             // iy*2 + ix
        int iy  = sub >> 1;
        int ix  = sub & 1;
        int ph  = bin / OUT_W;
        int pw  = bin - ph * OUT_W;

        float bin_h = rh * (1.0f / OUT_H);
        float bin_w = rw * (1.0f / OUT_W);
        float yy = -0.5f * rh + ((float)ph + ((float)iy + 0.5f) * 0.5f) * bin_h;
        float xx = -0.5f * rw + ((float)pw + ((float)ix + 0.5f) * 0.5f) * bin_w;

        float x = yy * sn + xx * cs + cx;
        float y = yy * cs - xx * sn + cy;

        bool valid = (y > -1.0f) && (y < (float)H_) && (x > -1.0f) && (x < (float)W_);
        y = fmaxf(y, 0.0f);
        x = fmaxf(x, 0.0f);

        int yl = (int)floorf(y);
        int xl = (int)floorf(x);
        float ly, lx;
        int dy, dx;
        if (yl >= H_ - 1) { yl = H_ - 1; dy = 0; ly = 0.0f; }
        else              { dy = 1;      ly = y - (float)yl; }
        if (xl >= W_ - 1) { xl = W_ - 1; dx = 0; lx = 0.0f; }
        else              { dx = 1;      lx = x - (float)xl; }

        int mi = sub * NBINS + bin;  // [sub][bin] SoA: lanes (consec bins) conflict-free
        s_off[mi] = yl * W_ + xl;
        s_pk [mi] = dx | ((dy * W_) << 4);
        s_lx [mi] = lx;
        s_ly [mi] = ly;
        s_sc [mi] = valid ? 0.25f : 0.0f;
    }
    __syncthreads();

    const int bofs = s_bofs;
    float* __restrict__ outr = out + (size_t)r * (C_ * NBINS);

    #pragma unroll 1
    for (int j = 0; j < NBINS; ++j) {
        int e   = j * 256 + t;               // 0 .. 12543
        int c   = e / NBINS;
        int bin = e - c * NBINS;
        const float* __restrict__ plane = feat + bofs + c * HW;

        float acc = 0.0f;
        #pragma unroll
        for (int s = 0; s < 4; ++s) {
            int   mi  = s * NBINS + bin;
            int   off = s_off[mi];
            int   pk  = s_pk [mi];
            float lx  = s_lx [mi];
            float ly  = s_ly [mi];
            float sc  = s_sc [mi];
            int dx  = pk & 1;
            int dyw = pk >> 4;

            float v1 = plane[off];
            float v2 = plane[off + dx];
            float v3 = plane[off + dyw];
            float v4 = plane[off + dyw + dx];

            float hy = 1.0f - ly;
            float hx = 1.0f - lx;
            float val = (hy * hx) * v1 + (hy * lx) * v2
                      + (ly * hx) * v3 + (ly * lx) * v4;
            acc = fmaf(sc, val, acc);
        }
        outr[e] = acc;
    }
}

extern "C" void kernel_launch(void* const* d_in, const int* in_sizes, int n_in,
                              void* d_out, int out_size)
{
    const float* feat = (const float*)d_in[0];   // [2,256,200,200] f32
    const float* rois = (const float*)d_in[1];   // [1000,6] f32
    float* out = (float*)d_out;                  // [1000,256,7,7] f32

    int R = in_sizes[1] / 6;                     // 1000
    roi_align_rotated_kernel<<<R, 256>>>(feat, rois, out);
}

// round 2
// speedup vs baseline: 1.0375x; 1.0375x over previous
#include <cuda_runtime.h>
#include <math.h>

#define OUT_H 7
#define OUT_W 7
#define NBINS 49            // 7*7
#define NSAMP 196           // 49 * 2 * 2 subsamples
#define C_ 256
#define H_ 200
#define W_ 200
#define HW (H_*W_)          // 40000
#define HW4 (HW/4)          // 10000 (float4 units)
#define W4  (W_/4)          // 50
#define SPATIAL_SCALE 0.25f

// Block = one roi, 256 threads.
// Phase 1: threads 0..195 precompute per-sample bilinear metadata:
//   b0  : float4 index of aligned window containing (v1,v2)
//   ds  : row step in float4 units (0 or 50)
//   wx  : float4 x-interp weights (hx/lx scattered by off&3, clamps folded in)
//   we  : spill weight for off&3==3 case (lx), 0 otherwise/invalid
//   why/wly : row weights * 0.25 * valid
// Phase 2: thread t<245 owns bin = t%49, channel group cg = t/49.
//   Channel loop c = 5k+cg  =>  element index e = 245k + t (contiguous stores).
//   All metadata in registers: hot loop = 8 LDG.128 + predicated fixups + FMAs.
__global__ __launch_bounds__(256, 3)
void roi_align_rotated_kernel(const float* __restrict__ feat,
                              const float* __restrict__ rois,
                              float* __restrict__ out)
{
    __shared__ int    s_b0 [NSAMP];
    __shared__ int    s_ds [NSAMP];
    __shared__ float4 s_wx [NSAMP];
    __shared__ float  s_why[NSAMP];
    __shared__ float  s_wly[NSAMP];
    __shared__ float  s_we [NSAMP];
    __shared__ int    s_bofs4;     // batch base offset in float4 units

    const int r = blockIdx.x;
    const int t = threadIdx.x;

    if (t < NSAMP) {
        const float* rr = rois + r * 6;
        float cx = rr[1] * SPATIAL_SCALE - 0.5f;
        float cy = rr[2] * SPATIAL_SCALE - 0.5f;
        float rw = rr[3] * SPATIAL_SCALE;
        float rh = rr[4] * SPATIAL_SCALE;
        float sn, cs;
        sincosf(rr[5], &sn, &cs);

        if (t == 0) s_bofs4 = (int)rr[0] * (C_ * HW4);

        int bin = t >> 2;            // 0..48
        int sub = t & 3;             // iy*2+ix
        int iy  = sub >> 1;
        int ix  = sub & 1;
        int ph  = bin / OUT_W;
        int pw  = bin - ph * OUT_W;

        float bin_h = rh * (1.0f / OUT_H);
        float bin_w = rw * (1.0f / OUT_W);
        float yy = -0.5f * rh + ((float)ph + ((float)iy + 0.5f) * 0.5f) * bin_h;
        float xx = -0.5f * rw + ((float)pw + ((float)ix + 0.5f) * 0.5f) * bin_w;

        float x = yy * sn + xx * cs + cx;
        float y = yy * cs - xx * sn + cy;

        bool valid = (y > -1.0f) && (y < (float)H_) && (x > -1.0f) && (x < (float)W_);
        y = fmaxf(y, 0.0f);
        x = fmaxf(x, 0.0f);

        int yl = (int)floorf(y);
        int xl = (int)floorf(x);
        float ly, lx;
        int dy;
        if (yl >= H_ - 1) { yl = H_ - 1; dy = 0; ly = 0.0f; }
        else              { dy = 1;      ly = y - (float)yl; }
        if (xl >= W_ - 1) { xl = W_ - 1; lx = 0.0f; }
        else              { lx = x - (float)xl; }
        float hy = 1.0f - ly;
        float hx = 1.0f - lx;

        int off = yl * W_ + xl;
        int a   = off & 3;

        float w0 = (a == 0) ? hx : 0.0f;
        float w1 = (a == 1) ? hx : ((a == 0) ? lx : 0.0f);
        float w2 = (a == 2) ? hx : ((a == 1) ? lx : 0.0f);
        float w3 = (a == 3) ? hx : ((a == 2) ? lx : 0.0f);
        float we = (a == 3 && valid) ? lx : 0.0f;

        float sc = valid ? 0.25f : 0.0f;

        int mi = sub * NBINS + bin;
        s_b0 [mi] = off >> 2;
        s_ds [mi] = dy * W4;
        s_wx [mi] = make_float4(w0, w1, w2, w3);
        s_why[mi] = sc * hy;
        s_wly[mi] = sc * ly;
        s_we [mi] = we;
    }
    __syncthreads();

    if (t >= 245) return;

    const int bin = t % 49;
    const int cg  = t / 49;                    // 0..4
    const int bofs4 = s_bofs4;

    // Hoist all metadata into registers (one-time LDS)
    int    b0[4], ds[4];
    float4 wx[4];
    float  why[4], wly[4], we[4];
    #pragma unroll
    for (int s = 0; s < 4; ++s) {
        int mi = s * NBINS + bin;
        b0[s]  = s_b0[mi];
        ds[s]  = s_ds[mi];
        wx[s]  = s_wx[mi];
        why[s] = s_why[mi];
        wly[s] = s_wly[mi];
        we[s]  = s_we[mi];
    }

    const float4* __restrict__ p4 = (const float4*)feat + bofs4 + cg * HW4;
    float* __restrict__ outp = out + (size_t)r * (C_ * NBINS) + t;

    #pragma unroll 1
    for (int k = 0; k < 52; ++k) {
        if (k == 51 && t >= 49) break;         // epilogue: only cg==0 does c=255

        float acc = 0.0f;
        #pragma unroll
        for (int s = 0; s < 4; ++s) {
            const float4* q = p4 + b0[s];
            float4 q0 = q[0];
            float4 q1 = q[ds[s]];

            float rx0 = q0.x * wx[s].x + q0.y * wx[s].y + q0.z * wx[s].z + q0.w * wx[s].w;
            float rx1 = q1.x * wx[s].x + q1.y * wx[s].y + q1.z * wx[s].z + q1.w * wx[s].w;

            if (we[s] != 0.0f) {               // off&3==3 spill: v2/v4 live in next float4
                const float* qe = (const float*)(q + 1);
                rx0 += we[s] * qe[0];
                rx1 += we[s] * qe[4 * ds[s]];
            }
            acc += why[s] * rx0 + wly[s] * rx1;
        }
        *outp = acc;
        outp += 245;
        p4   += 5 * HW4;                        // c += 5
    }
}

extern "C" void kernel_launch(void* const* d_in, const int* in_sizes, int n_in,
                              void* d_out, int out_size)
{
    const float* feat = (const float*)d_in[0];   // [2,256,200,200] f32
    const float* rois = (const float*)d_in[1];   // [1000,6] f32
    float* out = (float*)d_out;                  // [1000,256,7,7] f32

    int R = in_sizes[1] / 6;                     // 1000
    roi_align_rotated_kernel<<<R, 256>>>(feat, rois, out);
}

// round 3
// speedup vs baseline: 1.1424x; 1.1011x over previous
#include <cuda_runtime.h>
#include <math.h>

#define OUT_H 7
#define OUT_W 7
#define NBINS 49            // 7*7
#define NSAMP 196           // 49 * 2 * 2 subsamples
#define C_ 256
#define H_ 200
#define W_ 200
#define HW (H_*W_)          // 40000
#define HW4 (HW/4)          // 10000 (float4 units)
#define W4  (W_/4)          // 50
#define SPATIAL_SCALE 0.25f
#define CH_SPLIT 2          // blocks per roi (channel halves)
#define CH_PER_BLK (C_/CH_SPLIT)   // 128

// Grid = R * CH_SPLIT blocks, 256 threads each.
// Phase 1 (per block, threads 0..195): per-sample bilinear metadata:
//   pk  : (off>>2) | (dy<<15)   -- float4 window index + row-step flag
//   wx  : float4 x-interp weights (hx/lx scattered by off&3, clamps folded)
//   we  : spill weight for off&3==3 (lx * valid), else 0
//   why/wly : row weights * 0.25 * valid
// Phase 2: thread t<245 owns bin = t%49, cg = t/49 (0..4).
//   Channel c_local = 5k+cg over 26 iters (last iter only cg<3) -> 128 ch.
//   Element index within block-half: 245k + t  => contiguous stores.
__global__ __launch_bounds__(256, 4)
void roi_align_rotated_kernel(const float* __restrict__ feat,
                              const float* __restrict__ rois,
                              float* __restrict__ out)
{
    __shared__ int    s_pk [NSAMP];
    __shared__ float4 s_wx [NSAMP];
    __shared__ float  s_why[NSAMP];
    __shared__ float  s_wly[NSAMP];
    __shared__ float  s_we [NSAMP];
    __shared__ int    s_bofs4;     // batch base offset in float4 units

    const int r = blockIdx.x >> 1;          // roi
    const int h = blockIdx.x & 1;           // channel half
    const int t = threadIdx.x;

    if (t < NSAMP) {
        const float* rr = rois + r * 6;
        float cx = rr[1] * SPATIAL_SCALE - 0.5f;
        float cy = rr[2] * SPATIAL_SCALE - 0.5f;
        float rw = rr[3] * SPATIAL_SCALE;
        float rh = rr[4] * SPATIAL_SCALE;
        float sn, cs;
        sincosf(rr[5], &sn, &cs);

        if (t == 0) s_bofs4 = (int)rr[0] * (C_ * HW4);

        int bin = t >> 2;            // 0..48
        int sub = t & 3;             // iy*2+ix
        int iy  = sub >> 1;
        int ix  = sub & 1;
        int ph  = bin / OUT_W;
        int pw  = bin - ph * OUT_W;

        float bin_h = rh * (1.0f / OUT_H);
        float bin_w = rw * (1.0f / OUT_W);
        float yy = -0.5f * rh + ((float)ph + ((float)iy + 0.5f) * 0.5f) * bin_h;
        float xx = -0.5f * rw + ((float)pw + ((float)ix + 0.5f) * 0.5f) * bin_w;

        float x = yy * sn + xx * cs + cx;
        float y = yy * cs - xx * sn + cy;

        bool valid = (y > -1.0f) && (y < (float)H_) && (x > -1.0f) && (x < (float)W_);
        y = fmaxf(y, 0.0f);
        x = fmaxf(x, 0.0f);

        int yl = (int)floorf(y);
        int xl = (int)floorf(x);
        float ly, lx;
        int dy;
        if (yl >= H_ - 1) { yl = H_ - 1; dy = 0; ly = 0.0f; }
        else              { dy = 1;      ly = y - (float)yl; }
        if (xl >= W_ - 1) { xl = W_ - 1; lx = 0.0f; }
        else              { lx = x - (float)xl; }
        float hy = 1.0f - ly;
        float hx = 1.0f - lx;

        int off = yl * W_ + xl;
        int a   = off & 3;

        float w0 = (a == 0) ? hx : 0.0f;
        float w1 = (a == 1) ? hx : ((a == 0) ? lx : 0.0f);
        float w2 = (a == 2) ? hx : ((a == 1) ? lx : 0.0f);
        float w3 = (a == 3) ? hx : ((a == 2) ? lx : 0.0f);
        float we = (a == 3 && valid) ? lx : 0.0f;

        float sc = valid ? 0.25f : 0.0f;

        int mi = sub * NBINS + bin;
        s_pk [mi] = (off >> 2) | (dy << 15);
        s_wx [mi] = make_float4(w0, w1, w2, w3);
        s_why[mi] = sc * hy;
        s_wly[mi] = sc * ly;
        s_we [mi] = we;
    }
    __syncthreads();

    if (t >= 245) return;

    const int bin = t % 49;
    const int cg  = t / 49;                    // 0..4
    const int bofs4 = s_bofs4;

    // Hoist metadata into registers (one-time LDS). 8 regs per sample.
    int    pk[4];
    float4 wx[4];
    float  why[4], wly[4], we[4];
    #pragma unroll
    for (int s = 0; s < 4; ++s) {
        int mi = s * NBINS + bin;
        pk[s]  = s_pk[mi];
        wx[s]  = s_wx[mi];
        why[s] = s_why[mi];
        wly[s] = s_wly[mi];
        we[s]  = s_we[mi];
    }

    const float4* __restrict__ p4 =
        (const float4*)feat + bofs4 + (h * CH_PER_BLK + cg) * HW4;
    float* __restrict__ outp =
        out + (size_t)r * (C_ * NBINS) + h * (CH_PER_BLK * NBINS) + t;

    // c_local = 5k + cg in [0,128): k<25 full, k==25 only cg<3.
    const int niter = (cg < 3) ? 26 : 25;

    #pragma unroll 1
    for (int k = 0; k < niter; ++k) {
        float acc = 0.0f;
        #pragma unroll
        for (int s = 0; s < 4; ++s) {
            int b0 = pk[s] & 0x7FFF;
            int ds = (pk[s] >> 15) * W4;       // 0 or 50 float4s
            const float4* q = p4 + b0;
            float4 q0 = q[0];
            float4 q1 = q[ds];

            float rx0 = q0.x * wx[s].x + q0.y * wx[s].y + q0.z * wx[s].z + q0.w * wx[s].w;
            float rx1 = q1.x * wx[s].x + q1.y * wx[s].y + q1.z * wx[s].z + q1.w * wx[s].w;

            if (we[s] != 0.0f) {               // off&3==3 spill into next float4
                const float* qe = (const float*)(q + 1);
                rx0 += we[s] * qe[0];
                rx1 += we[s] * qe[4 * ds];
            }
            acc += why[s] * rx0 + wly[s] * rx1;
        }
        *outp = acc;
        outp += 245;
        p4   += 5 * HW4;                        // c_local += 5
    }
}

extern "C" void kernel_launch(void* const* d_in, const int* in_sizes, int n_in,
                              void* d_out, int out_size)
{
    const float* feat = (const float*)d_in[0];   // [2,256,200,200] f32
    const float* rois = (const float*)d_in[1];   // [1000,6] f32
    float* out = (float*)d_out;                  // [1000,256,7,7] f32

    int R = in_sizes[1] / 6;                     // 1000
    roi_align_rotated_kernel<<<R * CH_SPLIT, 256>>>(feat, rois, out);
}

// round 4
// speedup vs baseline: 3.7696x; 3.2999x over previous
#include <cuda_runtime.h>
#include <cuda_fp16.h>
#include <math.h>

#define OUT_H 7
#define OUT_W 7
#define NBINS 49
#define NSAMP 196
#define C_ 256
#define H_ 200
#define W_ 200
#define HW (H_*W_)
#define SPATIAL_SCALE 0.25f

// NHWC fp16 scratch: [B=2][H=200][W=200][C=256]  (163.84 MB, module-static)
__device__ __half g_nhwc[2 * H_ * W_ * C_];

// ---------------------------------------------------------------------------
// Kernel 1: NCHW fp32 -> NHWC fp16 transpose. 32x32 (x,c) tiles via smem.
// grid = (ceil(W/32)=7, B*H=400, C/32=8), block = (32,8).
// ---------------------------------------------------------------------------
__global__ __launch_bounds__(256)
void transpose_kernel(const float* __restrict__ feat)
{
    __shared__ float s[32][33];

    const int x0 = blockIdx.x * 32;
    const int by = blockIdx.y;          // b*H + y
    const int b  = by / H_;
    const int y  = by % H_;
    const int c0 = blockIdx.z * 32;
    const int tx = threadIdx.x;
    const int ty = threadIdx.y;

    const float* src = feat + ((size_t)(b * C_ + c0) * H_ + y) * W_;
    const int x = x0 + tx;
    #pragma unroll
    for (int i = 0; i < 4; ++i) {
        int cl = ty + 8 * i;
        if (x < W_) s[cl][tx] = src[(size_t)cl * HW + x];
    }
    __syncthreads();

    __half* dst = g_nhwc + ((size_t)(b * H_ + y) * W_ + x0) * C_ + c0;
    #pragma unroll
    for (int i = 0; i < 4; ++i) {
        int xr = ty + 8 * i;
        if (x0 + xr < W_) dst[(size_t)xr * C_ + tx] = __float2half(s[tx][xr]);
    }
}

// ---------------------------------------------------------------------------
// Kernel 2: gather from NHWC fp16. Block = 2 rois, 256 threads (8 warps).
// Warp owns a bin; lane l owns channels {2l,2l+1} (+64 offset), half2 loads
// => every corner load is one coalesced 128B line (1 L1 wavefront).
// Outputs staged in smem [c_local][bin] (stride-49 STS, conflict-free for
// the even-offset stores, 2-way for odd), flushed coalesced per 128-ch pass.
// ---------------------------------------------------------------------------
__global__ __launch_bounds__(256, 4)
void roi_gather_kernel(const float* __restrict__ rois,
                       float* __restrict__ out, int R)
{
    __shared__ int    s_base[NSAMP];   // element index of corner v1 (c=0)
    __shared__ int    s_dxe [NSAMP];   // dx * C_
    __shared__ int    s_dye [NSAMP];   // dy * W_ * C_
    __shared__ float4 s_w   [NSAMP];   // corner weights * 0.25 * valid
    __shared__ float  s_out [128 * NBINS];  // one 128-channel pass

    const int t = threadIdx.x;
    const int w = t >> 5;
    const int l = t & 31;
    const __half* __restrict__ g = g_nhwc;

    for (int rr = 0; rr < 2; ++rr) {
        const int r = blockIdx.x * 2 + rr;
        if (r >= R) return;
        if (rr) __syncthreads();

        if (t < NSAMP) {
            const float* rp = rois + r * 6;
            float cx = rp[1] * SPATIAL_SCALE - 0.5f;
            float cy = rp[2] * SPATIAL_SCALE - 0.5f;
            float rw = rp[3] * SPATIAL_SCALE;
            float rh = rp[4] * SPATIAL_SCALE;
            float sn, cs;
            sincosf(rp[5], &sn, &cs);
            int bofs = (int)rp[0] * HW;

            int bin = t >> 2;
            int sub = t & 3;
            int iy = sub >> 1, ix = sub & 1;
            int ph = bin / OUT_W;
            int pw = bin - ph * OUT_W;

            float bin_h = rh * (1.0f / OUT_H);
            float bin_w = rw * (1.0f / OUT_W);
            float yy = -0.5f * rh + ((float)ph + ((float)iy + 0.5f) * 0.5f) * bin_h;
            float xx = -0.5f * rw + ((float)pw + ((float)ix + 0.5f) * 0.5f) * bin_w;

            float x = yy * sn + xx * cs + cx;
            float y = yy * cs - xx * sn + cy;

            bool valid = (y > -1.0f) && (y < (float)H_) && (x > -1.0f) && (x < (float)W_);
            y = fmaxf(y, 0.0f);
            x = fmaxf(x, 0.0f);

            int yl = (int)floorf(y);
            int xl = (int)floorf(x);
            float ly, lx;
            int dy, dx;
            if (yl >= H_ - 1) { yl = H_ - 1; dy = 0; ly = 0.0f; }
            else              { dy = 1;      ly = y - (float)yl; }
            if (xl >= W_ - 1) { xl = W_ - 1; dx = 0; lx = 0.0f; }
            else              { dx = 1;      lx = x - (float)xl; }
            float hy = 1.0f - ly, hx = 1.0f - lx;
            float sc = valid ? 0.25f : 0.0f;

            s_base[t] = (bofs + yl * W_ + xl) * C_;
            s_dxe [t] = dx * C_;
            s_dye [t] = dy * (W_ * C_);
            s_w   [t] = make_float4(sc * hy * hx, sc * hy * lx,
                                    sc * ly * hx, sc * ly * lx);
        }
        __syncthreads();

        #pragma unroll 1
        for (int pass = 0; pass < 2; ++pass) {
            const int cofs = pass * 128 + 2 * l;   // global channel of acc0.x

            #pragma unroll 1
            for (int bin = w; bin < NBINS; bin += 8) {
                float2 acc0 = make_float2(0.0f, 0.0f);
                float2 acc1 = make_float2(0.0f, 0.0f);

                #pragma unroll
                for (int s = 0; s < 4; ++s) {
                    int mi  = bin * 4 + s;
                    int A   = s_base[mi] + cofs;
                    int dxe = s_dxe[mi];
                    int dye = s_dye[mi];
                    float4 wv = s_w[mi];

                    #pragma unroll
                    for (int m = 0; m < 2; ++m) {
                        int Ax = A + m * 64;
                        float2 v1 = __half22float2(*(const __half2*)(g + Ax));
                        float2 v2 = __half22float2(*(const __half2*)(g + Ax + dxe));
                        float2 v3 = __half22float2(*(const __half2*)(g + Ax + dye));
                        float2 v4 = __half22float2(*(const __half2*)(g + Ax + dye + dxe));
                        float2& acc = m ? acc1 : acc0;
                        acc.x += wv.x * v1.x + wv.y * v2.x + wv.z * v3.x + wv.w * v4.x;
                        acc.y += wv.x * v1.y + wv.y * v2.y + wv.z * v3.y + wv.w * v4.y;
                    }
                }
                int cl = 2 * l;   // channel within pass
                s_out[(cl     ) * NBINS + bin] = acc0.x;
                s_out[(cl +  1) * NBINS + bin] = acc0.y;
                s_out[(cl + 64) * NBINS + bin] = acc1.x;
                s_out[(cl + 65) * NBINS + bin] = acc1.y;
            }
            __syncthreads();

            // flush 128*49 = 6272 floats, coalesced
            float* op = out + (size_t)r * (C_ * NBINS) + pass * (128 * NBINS);
            #pragma unroll
            for (int j = 0; j < 25; ++j) {
                int idx = j * 256 + t;
                if (j < 24 || t < 128) op[idx] = s_out[idx];
            }
            __syncthreads();
        }
    }
}

extern "C" void kernel_launch(void* const* d_in, const int* in_sizes, int n_in,
                              void* d_out, int out_size)
{
    const float* feat = (const float*)d_in[0];   // [2,256,200,200] f32
    const float* rois = (const float*)d_in[1];   // [1000,6] f32
    float* out = (float*)d_out;                  // [1000,256,7,7] f32

    int R = in_sizes[1] / 6;

    dim3 tgrid((W_ + 31) / 32, 2 * H_, C_ / 32);
    dim3 tblk(32, 8);
    transpose_kernel<<<tgrid, tblk>>>(feat);

    roi_gather_kernel<<<(R + 1) / 2, 256>>>(rois, out, R);
}

// round 5
// speedup vs baseline: 4.4244x; 1.1737x over previous
#include <cuda_runtime.h>
#include <cuda_fp16.h>
#include <math.h>

#define OUT_H 7
#define OUT_W 7
#define NBINS 49
#define NSAMP 196
#define C_ 256
#define H_ 200
#define W_ 200
#define HW (H_*W_)
#define SPATIAL_SCALE 0.25f

// NHWC fp16 scratch: [B=2][H=200][W=200][C=256]  (163.84 MB)
__device__ __half g_nhwc[2 * H_ * W_ * C_];

// ---------------------------------------------------------------------------
// Kernel 1: NCHW fp32 -> NHWC fp16 transpose (unchanged from round 4).
// ---------------------------------------------------------------------------
__global__ __launch_bounds__(256)
void transpose_kernel(const float* __restrict__ feat)
{
    __shared__ float s[32][33];

    const int x0 = blockIdx.x * 32;
    const int by = blockIdx.y;          // b*H + y
    const int b  = by / H_;
    const int y  = by % H_;
    const int c0 = blockIdx.z * 32;
    const int tx = threadIdx.x;
    const int ty = threadIdx.y;

    const float* src = feat + ((size_t)(b * C_ + c0) * H_ + y) * W_;
    const int x = x0 + tx;
    #pragma unroll
    for (int i = 0; i < 4; ++i) {
        int cl = ty + 8 * i;
        if (x < W_) s[cl][tx] = src[(size_t)cl * HW + x];
    }
    __syncthreads();

    __half* dst = g_nhwc + ((size_t)(b * H_ + y) * W_ + x0) * C_ + c0;
    #pragma unroll
    for (int i = 0; i < 4; ++i) {
        int xr = ty + 8 * i;
        if (x0 + xr < W_) dst[(size_t)xr * C_ + tx] = __float2half(s[tx][xr]);
    }
}

// ---------------------------------------------------------------------------
// Kernel 2: gather. Block = (roi, channel-half). 256 threads, 8 warps.
// Warp owns a bin; lane l owns 4 contiguous channels 4l..4l+3 (LDG.64).
// Bilinear combine in half2 (HFMA2, weights pre-duplicated), one convert
// per sample, fp32 accumulation across the 4 subsamples.
// s_out uses channel swizzle c' = (c&3)*32 + (c>>2): STS lane stride 49
// (odd -> conflict-free), flush reads consecutive -> conflict-free.
// ---------------------------------------------------------------------------
__global__ __launch_bounds__(256, 6)
void roi_gather_kernel(const float* __restrict__ rois,
                       float* __restrict__ out)
{
    __shared__ int   s_base[NSAMP];   // element index of corner v1 (c=0)
    __shared__ int   s_dxe [NSAMP];   // dx * C_
    __shared__ int   s_dye [NSAMP];   // dy * W_ * C_
    __shared__ uint4 s_w   [NSAMP];   // 4 corner weights, each as dup half2
    __shared__ float s_out [128 * NBINS];

    const int r = blockIdx.x >> 1;
    const int h = blockIdx.x & 1;
    const int t = threadIdx.x;
    const int w = t >> 5;
    const int l = t & 31;
    const __half* __restrict__ g = g_nhwc;

    if (t < NSAMP) {
        const float* rp = rois + r * 6;
        float cx = rp[1] * SPATIAL_SCALE - 0.5f;
        float cy = rp[2] * SPATIAL_SCALE - 0.5f;
        float rw = rp[3] * SPATIAL_SCALE;
        float rh = rp[4] * SPATIAL_SCALE;
        float sn, cs;
        sincosf(rp[5], &sn, &cs);
        int bofs = (int)rp[0] * HW;

        int bin = t >> 2;
        int sub = t & 3;
        int iy = sub >> 1, ix = sub & 1;
        int ph = bin / OUT_W;
        int pw = bin - ph * OUT_W;

        float bin_h = rh * (1.0f / OUT_H);
        float bin_w = rw * (1.0f / OUT_W);
        float yy = -0.5f * rh + ((float)ph + ((float)iy + 0.5f) * 0.5f) * bin_h;
        float xx = -0.5f * rw + ((float)pw + ((float)ix + 0.5f) * 0.5f) * bin_w;

        float x = yy * sn + xx * cs + cx;
        float y = yy * cs - xx * sn + cy;

        bool valid = (y > -1.0f) && (y < (float)H_) && (x > -1.0f) && (x < (float)W_);
        y = fmaxf(y, 0.0f);
        x = fmaxf(x, 0.0f);

        int yl = (int)floorf(y);
        int xl = (int)floorf(x);
        float ly, lx;
        int dy, dx;
        if (yl >= H_ - 1) { yl = H_ - 1; dy = 0; ly = 0.0f; }
        else              { dy = 1;      ly = y - (float)yl; }
        if (xl >= W_ - 1) { xl = W_ - 1; dx = 0; lx = 0.0f; }
        else              { dx = 1;      lx = x - (float)xl; }
        float hy = 1.0f - ly, hx = 1.0f - lx;
        float sc = valid ? 0.25f : 0.0f;

        s_base[t] = (bofs + yl * W_ + xl) * C_;
        s_dxe [t] = dx * C_;
        s_dye [t] = dy * (W_ * C_);

        __half2 w1 = __half2half2(__float2half(sc * hy * hx));
        __half2 w2 = __half2half2(__float2half(sc * hy * lx));
        __half2 w3 = __half2half2(__float2half(sc * ly * hx));
        __half2 w4 = __half2half2(__float2half(sc * ly * lx));
        uint4 wp;
        wp.x = *(unsigned*)&w1; wp.y = *(unsigned*)&w2;
        wp.z = *(unsigned*)&w3; wp.w = *(unsigned*)&w4;
        s_w[t] = wp;
    }
    __syncthreads();

    const int cofs = h * 128 + 4 * l;    // global channel of lane's first ch
    const int sw_base = ((l & 7) != 0, (4 * l & 3), 0);  // (unused, keep simple)
    // swizzled row base for this lane's 4 channels c_local = 4l+j:
    //   c' = ((c&3)*32 + (c>>2)) = j*32 + l
    float* so = s_out + l * NBINS;       // + j*32*NBINS + bin

    #pragma unroll 1
    for (int bin = w; bin < NBINS; bin += 8) {
        float a0 = 0.f, a1 = 0.f, a2 = 0.f, a3 = 0.f;

        #pragma unroll
        for (int s = 0; s < 4; ++s) {
            int mi  = bin * 4 + s;
            int A   = s_base[mi] + cofs;
            int dxe = s_dxe[mi];
            int dye = s_dye[mi];
            uint4 wp = s_w[mi];
            __half2 w1 = *(__half2*)&wp.x, w2 = *(__half2*)&wp.y;
            __half2 w3 = *(__half2*)&wp.z, w4 = *(__half2*)&wp.w;

            uint2 q1 = *(const uint2*)(g + A);
            uint2 q2 = *(const uint2*)(g + A + dxe);
            uint2 q3 = *(const uint2*)(g + A + dye);
            uint2 q4 = *(const uint2*)(g + A + dye + dxe);

            __half2 lo = __hmul2(*(__half2*)&q1.x, w1);
            lo = __hfma2(*(__half2*)&q2.x, w2, lo);
            lo = __hfma2(*(__half2*)&q3.x, w3, lo);
            lo = __hfma2(*(__half2*)&q4.x, w4, lo);
            __half2 hi = __hmul2(*(__half2*)&q1.y, w1);
            hi = __hfma2(*(__half2*)&q2.y, w2, hi);
            hi = __hfma2(*(__half2*)&q3.y, w3, hi);
            hi = __hfma2(*(__half2*)&q4.y, w4, hi);

            float2 flo = __half22float2(lo);
            float2 fhi = __half22float2(hi);
            a0 += flo.x; a1 += flo.y; a2 += fhi.x; a3 += fhi.y;
        }
        so[0 * 32 * NBINS + bin] = a0;
        so[1 * 32 * NBINS + bin] = a1;
        so[2 * 32 * NBINS + bin] = a2;
        so[3 * 32 * NBINS + bin] = a3;
    }
    __syncthreads();

    // flush 128*49 = 6272 floats, coalesced; invert channel swizzle.
    float* op = out + (size_t)r * (C_ * NBINS) + h * (128 * NBINS);
    #pragma unroll
    for (int j = 0; j < 25; ++j) {
        int idx = j * 256 + t;
        if (j < 24 || t < 128) {
            int c   = idx / NBINS;
            int bin = idx - c * NBINS;
            op[idx] = s_out[((c & 3) * 32 + (c >> 2)) * NBINS + bin];
        }
    }
}

extern "C" void kernel_launch(void* const* d_in, const int* in_sizes, int n_in,
                              void* d_out, int out_size)
{
    const float* feat = (const float*)d_in[0];   // [2,256,200,200] f32
    const float* rois = (const float*)d_in[1];   // [1000,6] f32
    float* out = (float*)d_out;                  // [1000,256,7,7] f32

    int R = in_sizes[1] / 6;

    dim3 tgrid((W_ + 31) / 32, 2 * H_, C_ / 32);
    dim3 tblk(32, 8);
    transpose_kernel<<<tgrid, tblk>>>(feat);

    roi_gather_kernel<<<R * 2, 256>>>(rois, out);
}

// round 6
// speedup vs baseline: 4.6593x; 1.0531x over previous
#include <cuda_runtime.h>
#include <cuda_fp16.h>
#include <math.h>

#define OUT_H 7
#define OUT_W 7
#define NBINS 49
#define NSAMP 196
#define C_ 256
#define H_ 200
#define W_ 200
#define HW (H_*W_)
#define SPATIAL_SCALE 0.25f

// NHWC fp16 scratch: [B=2][H=200][W=200][C=256]  (41 MB)
__device__ __half g_nhwc[2 * H_ * W_ * C_];

// ---------------------------------------------------------------------------
// Kernel 1: NCHW fp32 -> NHWC fp16 transpose, half2-packed stores (128B/warp).
// Tile: 32 x-positions × 64 channels (32 half2 pairs). Block (32,8).
// grid = (7, B*H=400, C/64=4).
// ---------------------------------------------------------------------------
__global__ __launch_bounds__(256)
void transpose_kernel(const float* __restrict__ feat)
{
    __shared__ __half2 s2[32][33];     // [x][cpair], stride 33 -> conflict-free

    const int x0 = blockIdx.x * 32;
    const int by = blockIdx.y;          // b*H + y
    const int b  = by / H_;
    const int y  = by % H_;
    const int c0 = blockIdx.z * 64;
    const int tx = threadIdx.x;
    const int ty = threadIdx.y;

    const float* src = feat + ((size_t)(b * C_ + c0) * H_ + y) * W_;
    const int x = x0 + tx;
    #pragma unroll
    for (int i = 0; i < 4; ++i) {
        int p = ty + 8 * i;            // channel pair 0..31
        if (x < W_) {
            float f0 = src[(size_t)(2 * p    ) * HW + x];
            float f1 = src[(size_t)(2 * p + 1) * HW + x];
            s2[tx][p] = __floats2half2_rn(f0, f1);
        }
    }
    __syncthreads();

    __half* dst = g_nhwc + ((size_t)(b * H_ + y) * W_ + x0) * C_ + c0;
    #pragma unroll
    for (int i = 0; i < 4; ++i) {
        int xr = ty + 8 * i;
        if (x0 + xr < W_)
            *(__half2*)(dst + (size_t)xr * C_ + 2 * tx) = s2[xr][tx];
    }
}

// ---------------------------------------------------------------------------
// Kernel 2: gather. Block = roi, 256 threads, 8 warps.
// Warp handles a BIN PAIR per iteration: lanes 0-15 -> bin 2p, lanes 16-31 ->
// bin 2p+1. Lane owns 8 contiguous channels (LDG.128 per corner).
// Two channel passes (0..127, 128..255) staged in 128x49 smem with swizzle
// c' = (c&7)*16 + (c>>3) (STS and flush both conflict-free).
// ---------------------------------------------------------------------------
__global__ __launch_bounds__(256, 5)
void roi_gather_kernel(const float* __restrict__ rois,
                       float* __restrict__ out)
{
    __shared__ int   s_base[NSAMP];   // element index of corner v1 (c=0)
    __shared__ int   s_dxe [NSAMP];   // dx * C_
    __shared__ int   s_dye [NSAMP];   // dy * W_ * C_
    __shared__ uint4 s_w   [NSAMP];   // 4 corner weights as dup half2
    __shared__ float s_out [128 * NBINS];

    const int r  = blockIdx.x;
    const int t  = threadIdx.x;
    const int w  = t >> 5;
    const int l  = t & 31;
    const int sub = l >> 4;            // which bin of the pair
    const int lh  = l & 15;            // channel lane within 128-ch half
    const __half* __restrict__ g = g_nhwc;

    if (t < NSAMP) {
        const float* rp = rois + r * 6;
        float cx = rp[1] * SPATIAL_SCALE - 0.5f;
        float cy = rp[2] * SPATIAL_SCALE - 0.5f;
        float rw = rp[3] * SPATIAL_SCALE;
        float rh = rp[4] * SPATIAL_SCALE;
        float sn, cs;
        sincosf(rp[5], &sn, &cs);
        int bofs = (int)rp[0] * HW;

        int bin = t >> 2;
        int su  = t & 3;
        int iy = su >> 1, ix = su & 1;
        int ph = bin / OUT_W;
        int pw = bin - ph * OUT_W;

        float bin_h = rh * (1.0f / OUT_H);
        float bin_w = rw * (1.0f / OUT_W);
        float yy = -0.5f * rh + ((float)ph + ((float)iy + 0.5f) * 0.5f) * bin_h;
        float xx = -0.5f * rw + ((float)pw + ((float)ix + 0.5f) * 0.5f) * bin_w;

        float x = yy * sn + xx * cs + cx;
        float y = yy * cs - xx * sn + cy;

        bool valid = (y > -1.0f) && (y < (float)H_) && (x > -1.0f) && (x < (float)W_);
        y = fmaxf(y, 0.0f);
        x = fmaxf(x, 0.0f);

        int yl = (int)floorf(y);
        int xl = (int)floorf(x);
        float ly, lx;
        int dy, dx;
        if (yl >= H_ - 1) { yl = H_ - 1; dy = 0; ly = 0.0f; }
        else              { dy = 1;      ly = y - (float)yl; }
        if (xl >= W_ - 1) { xl = W_ - 1; dx = 0; lx = 0.0f; }
        else              { dx = 1;      lx = x - (float)xl; }
        float hy = 1.0f - ly, hx = 1.0f - lx;
        float sc = valid ? 0.25f : 0.0f;

        s_base[t] = (bofs + yl * W_ + xl) * C_;
        s_dxe [t] = dx * C_;
        s_dye [t] = dy * (W_ * C_);

        __half2 w1 = __half2half2(__float2half(sc * hy * hx));
        __half2 w2 = __half2half2(__float2half(sc * hy * lx));
        __half2 w3 = __half2half2(__float2half(sc * ly * hx));
        __half2 w4 = __half2half2(__float2half(sc * ly * lx));
        uint4 wp;
        wp.x = *(unsigned*)&w1; wp.y = *(unsigned*)&w2;
        wp.z = *(unsigned*)&w3; wp.w = *(unsigned*)&w4;
        s_w[t] = wp;
    }
    __syncthreads();

    #pragma unroll 1
    for (int pass = 0; pass < 2; ++pass) {
        const int cofs = pass * 128 + 8 * lh;   // global channel of lane's c0

        #pragma unroll 1
        for (int p = w; p < 25; p += 8) {
            int bin  = 2 * p + sub;
            int binc = (bin < NBINS) ? bin : (NBINS - 1);

            float a0 = 0.f, a1 = 0.f, a2 = 0.f, a3 = 0.f;
            float a4 = 0.f, a5 = 0.f, a6 = 0.f, a7 = 0.f;

            #pragma unroll
            for (int s = 0; s < 4; ++s) {
                int mi  = binc * 4 + s;
                int A   = s_base[mi] + cofs;
                int dxe = s_dxe[mi];
                int dye = s_dye[mi];
                uint4 wp = s_w[mi];
                __half2 w1 = *(__half2*)&wp.x, w2 = *(__half2*)&wp.y;
                __half2 w3 = *(__half2*)&wp.z, w4 = *(__half2*)&wp.w;

                uint4 q1 = *(const uint4*)(g + A);
                uint4 q2 = *(const uint4*)(g + A + dxe);
                uint4 q3 = *(const uint4*)(g + A + dye);
                uint4 q4 = *(const uint4*)(g + A + dye + dxe);

                __half2 h0 = __hmul2(*(__half2*)&q1.x, w1);
                h0 = __hfma2(*(__half2*)&q2.x, w2, h0);
                h0 = __hfma2(*(__half2*)&q3.x, w3, h0);
                h0 = __hfma2(*(__half2*)&q4.x, w4, h0);
                __half2 h1 = __hmul2(*(__half2*)&q1.y, w1);
                h1 = __hfma2(*(__half2*)&q2.y, w2, h1);
                h1 = __hfma2(*(__half2*)&q3.y, w3, h1);
                h1 = __hfma2(*(__half2*)&q4.y, w4, h1);
                __half2 h2 = __hmul2(*(__half2*)&q1.z, w1);
                h2 = __hfma2(*(__half2*)&q2.z, w2, h2);
                h2 = __hfma2(*(__half2*)&q3.z, w3, h2);
                h2 = __hfma2(*(__half2*)&q4.z, w4, h2);
                __half2 h3 = __hmul2(*(__half2*)&q1.w, w1);
                h3 = __hfma2(*(__half2*)&q2.w, w2, h3);
                h3 = __hfma2(*(__half2*)&q3.w, w3, h3);
                h3 = __hfma2(*(__half2*)&q4.w, w4, h3);

                float2 f0 = __half22float2(h0);
                float2 f1 = __half22float2(h1);
                float2 f2 = __half22float2(h2);
                float2 f3 = __half22float2(h3);
                a0 += f0.x; a1 += f0.y; a2 += f1.x; a3 += f1.y;
                a4 += f2.x; a5 += f2.y; a6 += f3.x; a7 += f3.y;
            }

            if (bin < NBINS) {
                // c_local = 8*lh + j  ->  c' = j*16 + lh
                float* so = s_out + lh * NBINS + bin;
                so[ 0 * 16 * NBINS] = a0;
                so[ 1 * 16 * NBINS] = a1;
                so[ 2 * 16 * NBINS] = a2;
                so[ 3 * 16 * NBINS] = a3;
                so[ 4 * 16 * NBINS] = a4;
                so[ 5 * 16 * NBINS] = a5;
                so[ 6 * 16 * NBINS] = a6;
                so[ 7 * 16 * NBINS] = a7;
            }
        }
        __syncthreads();

        // flush 128*49 = 6272 floats, coalesced; invert channel swizzle.
        float* op = out + (size_t)r * (C_ * NBINS) + pass * (128 * NBINS);
        #pragma unroll
        for (int j = 0; j < 25; ++j) {
            int idx = j * 256 + t;
            if (j < 24 || t < 128) {
                int c   = idx / NBINS;
                int bin = idx - c * NBINS;
                op[idx] = s_out[((c & 7) * 16 + (c >> 3)) * NBINS + bin];
            }
        }
        __syncthreads();
    }
}

extern "C" void kernel_launch(void* const* d_in, const int* in_sizes, int n_in,
                              void* d_out, int out_size)
{
    const float* feat = (const float*)d_in[0];   // [2,256,200,200] f32
    const float* rois = (const float*)d_in[1];   // [1000,6] f32
    float* out = (float*)d_out;                  // [1000,256,7,7] f32

    int R = in_sizes[1] / 6;

    dim3 tgrid((W_ + 31) / 32, 2 * H_, C_ / 64);
    dim3 tblk(32, 8);
    transpose_kernel<<<tgrid, tblk>>>(feat);

    roi_gather_kernel<<<R, 256>>>(rois, out);
}

// round 7
// speedup vs baseline: 5.0971x; 1.0940x over previous
#include <cuda_runtime.h>
#include <cuda_fp16.h>
#include <math.h>

#define OUT_H 7
#define OUT_W 7
#define NBINS 49
#define NSAMP 196
#define C_ 256
#define H_ 200
#define W_ 200
#define HW (H_*W_)
#define SPATIAL_SCALE 0.25f

// NHWC fp16 scratch: [B=2][H=200][W=200][C=256]  (41 MB)
__device__ __half g_nhwc[2 * H_ * W_ * C_];

// ---------------------------------------------------------------------------
// Kernel 1: NCHW fp32 -> NHWC fp16 transpose, half2-packed stores (128B/warp).
// Tile: 32 x-positions × 64 channels (32 half2 pairs). Block (32,8).
// grid = (7, B*H=400, C/64=4).
// ---------------------------------------------------------------------------
__global__ __launch_bounds__(256)
void transpose_kernel(const float* __restrict__ feat)
{
    __shared__ __half2 s2[32][33];     // [x][cpair], stride 33 -> conflict-free

    const int x0 = blockIdx.x * 32;
    const int by = blockIdx.y;          // b*H + y
    const int b  = by / H_;
    const int y  = by % H_;
    const int c0 = blockIdx.z * 64;
    const int tx = threadIdx.x;
    const int ty = threadIdx.y;

    const float* src = feat + ((size_t)(b * C_ + c0) * H_ + y) * W_;
    const int x = x0 + tx;
    #pragma unroll
    for (int i = 0; i < 4; ++i) {
        int p = ty + 8 * i;            // channel pair 0..31
        if (x < W_) {
            float f0 = src[(size_t)(2 * p    ) * HW + x];
            float f1 = src[(size_t)(2 * p + 1) * HW + x];
            s2[tx][p] = __floats2half2_rn(f0, f1);
        }
    }
    __syncthreads();

    __half* dst = g_nhwc + ((size_t)(b * H_ + y) * W_ + x0) * C_ + c0;
    #pragma unroll
    for (int i = 0; i < 4; ++i) {
        int xr = ty + 8 * i;
        if (x0 + xr < W_)
            *(__half2*)(dst + (size_t)xr * C_ + 2 * tx) = s2[xr][tx];
    }
}

// ---------------------------------------------------------------------------
// Kernel 2: gather (round-5 proven config). Block = (roi, channel-half).
// 256 threads, 8 warps. Warp owns a bin; lane l owns 4 contiguous channels
// 4l..4l+3 (LDG.64 per corner). HFMA2 bilinear combine (weights duplicated
// into half2), one convert pair per sample, fp32 accumulation across the 4
// subsamples. s_out channel swizzle c' = (c&3)*32 + (c>>2): STS lane stride
// 49 (odd -> conflict-free), flush reads consecutive -> conflict-free.
// ---------------------------------------------------------------------------
__global__ __launch_bounds__(256, 6)
void roi_gather_kernel(const float* __restrict__ rois,
                       float* __restrict__ out)
{
    __shared__ int   s_base[NSAMP];   // element index of corner v1 (c=0)
    __shared__ int   s_dxe [NSAMP];   // dx * C_
    __shared__ int   s_dye [NSAMP];   // dy * W_ * C_
    __shared__ uint4 s_w   [NSAMP];   // 4 corner weights, each as dup half2
    __shared__ float s_out [128 * NBINS];

    const int r = blockIdx.x >> 1;
    const int h = blockIdx.x & 1;
    const int t = threadIdx.x;
    const int w = t >> 5;
    const int l = t & 31;
    const __half* __restrict__ g = g_nhwc;

    if (t < NSAMP) {
        const float* rp = rois + r * 6;
        float cx = rp[1] * SPATIAL_SCALE - 0.5f;
        float cy = rp[2] * SPATIAL_SCALE - 0.5f;
        float rw = rp[3] * SPATIAL_SCALE;
        float rh = rp[4] * SPATIAL_SCALE;
        float sn, cs;
        sincosf(rp[5], &sn, &cs);
        int bofs = (int)rp[0] * HW;

        int bin = t >> 2;
        int sub = t & 3;
        int iy = sub >> 1, ix = sub & 1;
        int ph = bin / OUT_W;
        int pw = bin - ph * OUT_W;

        float bin_h = rh * (1.0f / OUT_H);
        float bin_w = rw * (1.0f / OUT_W);
        float yy = -0.5f * rh + ((float)ph + ((float)iy + 0.5f) * 0.5f) * bin_h;
        float xx = -0.5f * rw + ((float)pw + ((float)ix + 0.5f) * 0.5f) * bin_w;

        float x = yy * sn + xx * cs + cx;
        float y = yy * cs - xx * sn + cy;

        bool valid = (y > -1.0f) && (y < (float)H_) && (x > -1.0f) && (x < (float)W_);
        y = fmaxf(y, 0.0f);
        x = fmaxf(x, 0.0f);

        int yl = (int)floorf(y);
        int xl = (int)floorf(x);
        float ly, lx;
        int dy, dx;
        if (yl >= H_ - 1) { yl = H_ - 1; dy = 0; ly = 0.0f; }
        else              { dy = 1;      ly = y - (float)yl; }
        if (xl >= W_ - 1) { xl = W_ - 1; dx = 0; lx = 0.0f; }
        else              { dx = 1;      lx = x - (float)xl; }
        float hy = 1.0f - ly, hx = 1.0f - lx;
        float sc = valid ? 0.25f : 0.0f;

        s_base[t] = (bofs + yl * W_ + xl) * C_;
        s_dxe [t] = dx * C_;
        s_dye [t] = dy * (W_ * C_);

        __half2 w1 = __half2half2(__float2half(sc * hy * hx));
        __half2 w2 = __half2half2(__float2half(sc * hy * lx));
        __half2 w3 = __half2half2(__float2half(sc * ly * hx));
        __half2 w4 = __half2half2(__float2half(sc * ly * lx));
        uint4 wp;
        wp.x = *(unsigned*)&w1; wp.y = *(unsigned*)&w2;
        wp.z = *(unsigned*)&w3; wp.w = *(unsigned*)&w4;
        s_w[t] = wp;
    }
    __syncthreads();

    const int cofs = h * 128 + 4 * l;    // global channel of lane's first ch
    float* so = s_out + l * NBINS;       // + j*32*NBINS + bin  (c' = j*32+l)

    #pragma unroll 1
    for (int bin = w; bin < NBINS; bin += 8) {
        float a0 = 0.f, a1 = 0.f, a2 = 0.f, a3 = 0.f;

        #pragma unroll
        for (int s = 0; s < 4; ++s) {
            int mi  = bin * 4 + s;
            int A   = s_base[mi] + cofs;
            int dxe = s_dxe[mi];
            int dye = s_dye[mi];
            uint4 wp = s_w[mi];
            __half2 w1 = *(__half2*)&wp.x, w2 = *(__half2*)&wp.y;
            __half2 w3 = *(__half2*)&wp.z, w4 = *(__half2*)&wp.w;

            uint2 q1 = *(const uint2*)(g + A);
            uint2 q2 = *(const uint2*)(g + A + dxe);
            uint2 q3 = *(const uint2*)(g + A + dye);
            uint2 q4 = *(const uint2*)(g + A + dye + dxe);

            __half2 lo = __hmul2(*(__half2*)&q1.x, w1);
            lo = __hfma2(*(__half2*)&q2.x, w2, lo);
            lo = __hfma2(*(__half2*)&q3.x, w3, lo);
            lo = __hfma2(*(__half2*)&q4.x, w4, lo);
            __half2 hi = __hmul2(*(__half2*)&q1.y, w1);
            hi = __hfma2(*(__half2*)&q2.y, w2, hi);
            hi = __hfma2(*(__half2*)&q3.y, w3, hi);
            hi = __hfma2(*(__half2*)&q4.y, w4, hi);

            float2 flo = __half22float2(lo);
            float2 fhi = __half22float2(hi);
            a0 += flo.x; a1 += flo.y; a2 += fhi.x; a3 += fhi.y;
        }
        so[0 * 32 * NBINS + bin] = a0;
        so[1 * 32 * NBINS + bin] = a1;
        so[2 * 32 * NBINS + bin] = a2;
        so[3 * 32 * NBINS + bin] = a3;
    }
    __syncthreads();

    // flush 128*49 = 6272 floats, coalesced; invert channel swizzle.
    float* op = out + (size_t)r * (C_ * NBINS) + h * (128 * NBINS);
    #pragma unroll
    for (int j = 0; j < 25; ++j) {
        int idx = j * 256 + t;
        if (j < 24 || t < 128) {
            int c   = idx / NBINS;
            int bin = idx - c * NBINS;
            op[idx] = s_out[((c & 3) * 32 + (c >> 2)) * NBINS + bin];
        }
    }
}

extern "C" void kernel_launch(void* const* d_in, const int* in_sizes, int n_in,
                              void* d_out, int out_size)
{
    const float* feat = (const float*)d_in[0];   // [2,256,200,200] f32
    const float* rois = (const float*)d_in[1];   // [1000,6] f32
    float* out = (float*)d_out;                  // [1000,256,7,7] f32

    int R = in_sizes[1] / 6;

    dim3 tgrid((W_ + 31) / 32, 2 * H_, C_ / 64);
    dim3 tblk(32, 8);
    transpose_kernel<<<tgrid, tblk>>>(feat);

    roi_gather_kernel<<<R * 2, 256>>>(rois, out);
}